// round 7
// baseline (speedup 1.0000x reference)
#include <cuda_runtime.h>
#include <cuda_bf16.h>
#include <cstdint>

#define NN 50000
#define EE 800000
#define KPAD 136   // bf16 elems per SMEM row (272B) -> conflict-free fragments

// ---------------- scratch (static device globals) --------------------------
__device__ float g_Y[NN * 128];
__device__ float g_H[NN * 128];
__device__ float g_dinv[NN];
__device__ int   g_deg[NN];        // edge-only degree; zeroed by scan_final for next replay
__device__ int   g_cursor[NN];
__device__ int   g_rowptr[NN + 1];
__device__ int   g_csrc[EE];
__device__ int   g_bsum[64];
// pre-split, pre-transposed weights: [N][K=128] bf16, hi + lo parts
__device__ __nv_bfloat16 g_W1h[128 * 128], g_W1l[128 * 128];
__device__ __nv_bfloat16 g_W2h[128 * 128], g_W2l[128 * 128];
__device__ __nv_bfloat16 g_W3h[64 * 128],  g_W3l[64 * 128];

// ---------------- preprocessing ---------------------------------------------

// 4 edges per thread: 4 independent atomics in flight (E % 4 == 0 path + tail)
__global__ void count_k(const int* __restrict__ ei, int E) {
    int t = blockIdx.x * blockDim.x + threadIdx.x;
    int e0 = t * 4;
    if (e0 + 4 <= E) {
        int4 d = *(const int4*)(ei + E + e0);
        atomicAdd(&g_deg[d.x], 1);
        atomicAdd(&g_deg[d.y], 1);
        atomicAdd(&g_deg[d.z], 1);
        atomicAdd(&g_deg[d.w], 1);
    } else {
        for (int e = e0; e < E; e++) atomicAdd(&g_deg[ei[E + e]], 1);
    }
}

__device__ __forceinline__ void conv_one(const float* W, __nv_bfloat16* Wh,
                                         __nv_bfloat16* Wl, int F, int idx) {
    int nn = idx >> 7, k = idx & 127;
    float v = W[k * F + nn];
    __nv_bfloat16 h = __float2bfloat16(v);
    __nv_bfloat16 l = __float2bfloat16(v - __bfloat162float(h));
    Wh[nn * 128 + k] = h;
    Wl[nn * 128 + k] = l;
}

// blocks [0, nbS): dinv + per-1024-chunk partial sums of edge-degree
// blocks [nbS, nbS+CONVB): weight split/transpose for all 3 layers
#define CONVB 10
__global__ void scanconv_k(int n, int nbS,
                           const float* __restrict__ W1,
                           const float* __restrict__ W2,
                           const float* __restrict__ W3) {
    int bid = blockIdx.x;
    int tid = threadIdx.x;
    if (bid >= nbS) {
        for (int idx = (bid - nbS) * 1024 + tid; idx < 40960; idx += CONVB * 1024) {
            if (idx < 16384)       conv_one(W1, g_W1h, g_W1l, 128, idx);
            else if (idx < 32768)  conv_one(W2, g_W2h, g_W2l, 128, idx - 16384);
            else                   conv_one(W3, g_W3h, g_W3l, 64,  idx - 32768);
        }
        return;
    }
    __shared__ int sm[32];
    int i = bid * 1024 + tid;
    int v = 0;
    if (i < n) {
        v = g_deg[i];                       // edge-only degree
        g_dinv[i] = rsqrtf((float)(v + 1)); // +1 self-loop
    }
    int vv = v;
    #pragma unroll
    for (int o = 16; o > 0; o >>= 1) vv += __shfl_down_sync(0xffffffffu, vv, o);
    int lane = tid & 31, wid = tid >> 5;
    if (lane == 0) sm[wid] = vv;
    __syncthreads();
    if (wid == 0) {
        vv = sm[lane];
        #pragma unroll
        for (int o = 16; o > 0; o >>= 1) vv += __shfl_down_sync(0xffffffffu, vv, o);
        if (lane == 0) g_bsum[bid] = vv;
    }
}

// rowptr + cursor + zero deg; each block computes its own bsum-prefix (nbS<=64)
__global__ void scan_final_k(int n, int nbS) {
    __shared__ int sm[1024];
    __shared__ int s_off;
    int tid = threadIdx.x;
    int bid = blockIdx.x;
    int i = bid * 1024 + tid;

    if (tid < 32) {
        int a = (tid      < bid) ? g_bsum[tid]      : 0;
        int b = (tid + 32 < bid) ? g_bsum[tid + 32] : 0;
        int s = a + b;
        #pragma unroll
        for (int o = 16; o > 0; o >>= 1) s += __shfl_down_sync(0xffffffffu, s, o);
        if (tid == 0) s_off = s;
    }

    int v = 0;
    if (i < n) {
        v = g_deg[i];
        g_deg[i] = 0;                        // reset for next graph replay
    }
    sm[tid] = v;
    __syncthreads();
    #pragma unroll
    for (int off = 1; off < 1024; off <<= 1) {
        int t = 0;
        if (tid >= off) t = sm[tid - off];
        __syncthreads();
        if (tid >= off) sm[tid] += t;
        __syncthreads();
    }
    int incl = sm[tid];
    if (i < n) {
        int rp = s_off + incl - v;
        g_rowptr[i] = rp;
        g_cursor[i] = rp;
        if (i == n - 1) g_rowptr[n] = s_off + incl;
    }
}

// 4 edges per thread: 4 independent atomic+store chains
__global__ void fill_k(const int* __restrict__ ei, int E) {
    int t = blockIdx.x * blockDim.x + threadIdx.x;
    int e0 = t * 4;
    if (e0 + 4 <= E) {
        int4 s = *(const int4*)(ei + e0);
        int4 d = *(const int4*)(ei + E + e0);
        int p0 = atomicAdd(&g_cursor[d.x], 1);
        int p1 = atomicAdd(&g_cursor[d.y], 1);
        int p2 = atomicAdd(&g_cursor[d.z], 1);
        int p3 = atomicAdd(&g_cursor[d.w], 1);
        g_csrc[p0] = s.x;
        g_csrc[p1] = s.y;
        g_csrc[p2] = s.z;
        g_csrc[p3] = s.w;
    } else {
        for (int e = e0; e < E; e++) {
            int pos = atomicAdd(&g_cursor[ei[E + e]], 1);
            g_csrc[pos] = ei[e];
        }
    }
}

// ---------------- tensor-core GEMM ------------------------------------------
// Y[n,F] = (relu?(A[n,128]) @ W[128,F]) * dinv[row],  bf16x3 split for fp32.

__device__ __forceinline__ unsigned packbf(float a, float b) {
    __nv_bfloat162 p = __floats2bfloat162_rn(a, b);
    return *reinterpret_cast<unsigned*>(&p);
}

__device__ __forceinline__ void mma_bf16(float* c,
                                         unsigned a0, unsigned a1, unsigned a2, unsigned a3,
                                         unsigned b0, unsigned b1) {
    asm volatile(
        "mma.sync.aligned.m16n8k16.row.col.f32.bf16.bf16.f32 "
        "{%0,%1,%2,%3}, {%4,%5,%6,%7}, {%8,%9}, {%0,%1,%2,%3};"
        : "+f"(c[0]), "+f"(c[1]), "+f"(c[2]), "+f"(c[3])
        : "r"(a0), "r"(a1), "r"(a2), "r"(a3), "r"(b0), "r"(b1));
}

template <int F, bool RELU>
__global__ __launch_bounds__(256)
void gemm_tc(const float* __restrict__ A,
             const __nv_bfloat16* __restrict__ Wh,
             const __nv_bfloat16* __restrict__ Wl, int n) {
    extern __shared__ unsigned char smraw[];
    __nv_bfloat16* sWh = (__nv_bfloat16*)smraw;        // F * KPAD
    __nv_bfloat16* sWl = sWh + F * KPAD;
    __nv_bfloat16* sAh = sWl + F * KPAD;               // 128 * KPAD
    __nv_bfloat16* sAl = sAh + 128 * KPAD;

    const int NT = F / 16;
    int tid = threadIdx.x;
    int wid = tid >> 5, lane = tid & 31;
    int g = lane >> 2, t = lane & 3;
    int wm = wid >> 1;
    int wn = wid & 1;
    int arow = wm * 32;
    int bcol0 = wn * (F / 2);

    {
        const unsigned* gwh = (const unsigned*)Wh;
        const unsigned* gwl = (const unsigned*)Wl;
        for (int i = tid; i < F * 64; i += 256) {
            int r = i >> 6, c = i & 63;
            ((unsigned*)(sWh + r * KPAD))[c] = gwh[i];
            ((unsigned*)(sWl + r * KPAD))[c] = gwl[i];
        }
    }

    int ntiles = (n + 127) >> 7;
    for (int tile = blockIdx.x; tile < ntiles; tile += gridDim.x) {
        __syncthreads();
        int r0 = tile * 128;

        for (int i = tid; i < 4096; i += 256) {
            int r = i >> 5, c4 = i & 31;
            int row = r0 + r;
            float4 v = make_float4(0.f, 0.f, 0.f, 0.f);
            if (row < n) v = *(const float4*)(A + (size_t)row * 128 + c4 * 4);
            if (RELU) {
                v.x = fmaxf(v.x, 0.f); v.y = fmaxf(v.y, 0.f);
                v.z = fmaxf(v.z, 0.f); v.w = fmaxf(v.w, 0.f);
            }
            __nv_bfloat16 h0 = __float2bfloat16(v.x), h1 = __float2bfloat16(v.y);
            __nv_bfloat16 h2 = __float2bfloat16(v.z), h3 = __float2bfloat16(v.w);
            float l0 = v.x - __bfloat162float(h0), l1 = v.y - __bfloat162float(h1);
            float l2 = v.z - __bfloat162float(h2), l3 = v.w - __bfloat162float(h3);
            unsigned h01, h23;
            { __nv_bfloat162 p0 = {h0, h1}; h01 = *reinterpret_cast<unsigned*>(&p0);
              __nv_bfloat162 p1 = {h2, h3}; h23 = *reinterpret_cast<unsigned*>(&p1); }
            unsigned l01 = packbf(l0, l1), l23 = packbf(l2, l3);
            *reinterpret_cast<uint2*>(sAh + r * KPAD + c4 * 4) = make_uint2(h01, h23);
            *reinterpret_cast<uint2*>(sAl + r * KPAD + c4 * 4) = make_uint2(l01, l23);
        }
        __syncthreads();

        float acc[2][NT][4];
        #pragma unroll
        for (int rb = 0; rb < 2; rb++)
            #pragma unroll
            for (int j = 0; j < NT; j++) {
                acc[rb][j][0] = 0.f; acc[rb][j][1] = 0.f;
                acc[rb][j][2] = 0.f; acc[rb][j][3] = 0.f;
            }

        #pragma unroll
        for (int kk = 0; kk < 128; kk += 16) {
            unsigned ah[2][4], al[2][4];
            #pragma unroll
            for (int rb = 0; rb < 2; rb++) {
                int br = arow + rb * 16;
                ah[rb][0] = *(const unsigned*)(sAh + (br + g)     * KPAD + kk + 2 * t);
                ah[rb][1] = *(const unsigned*)(sAh + (br + g + 8) * KPAD + kk + 2 * t);
                ah[rb][2] = *(const unsigned*)(sAh + (br + g)     * KPAD + kk + 8 + 2 * t);
                ah[rb][3] = *(const unsigned*)(sAh + (br + g + 8) * KPAD + kk + 8 + 2 * t);
                al[rb][0] = *(const unsigned*)(sAl + (br + g)     * KPAD + kk + 2 * t);
                al[rb][1] = *(const unsigned*)(sAl + (br + g + 8) * KPAD + kk + 2 * t);
                al[rb][2] = *(const unsigned*)(sAl + (br + g)     * KPAD + kk + 8 + 2 * t);
                al[rb][3] = *(const unsigned*)(sAl + (br + g + 8) * KPAD + kk + 8 + 2 * t);
            }
            #pragma unroll
            for (int j = 0; j < NT; j++) {
                int bn = bcol0 + j * 8 + g;
                unsigned b0h = *(const unsigned*)(sWh + bn * KPAD + kk + 2 * t);
                unsigned b1h = *(const unsigned*)(sWh + bn * KPAD + kk + 8 + 2 * t);
                unsigned b0l = *(const unsigned*)(sWl + bn * KPAD + kk + 2 * t);
                unsigned b1l = *(const unsigned*)(sWl + bn * KPAD + kk + 8 + 2 * t);
                #pragma unroll
                for (int rb = 0; rb < 2; rb++) {
                    mma_bf16(acc[rb][j], ah[rb][0], ah[rb][1], ah[rb][2], ah[rb][3], b0h, b1h);
                    mma_bf16(acc[rb][j], ah[rb][0], ah[rb][1], ah[rb][2], ah[rb][3], b0l, b1l);
                    mma_bf16(acc[rb][j], al[rb][0], al[rb][1], al[rb][2], al[rb][3], b0h, b1h);
                }
            }
        }

        #pragma unroll
        for (int rb = 0; rb < 2; rb++) {
            int row0 = r0 + arow + rb * 16 + g;
            int row1 = row0 + 8;
            float d0 = (row0 < n) ? g_dinv[row0] : 0.f;
            float d1 = (row1 < n) ? g_dinv[row1] : 0.f;
            #pragma unroll
            for (int j = 0; j < NT; j++) {
                int col = bcol0 + j * 8 + 2 * t;
                if (row0 < n) {
                    float2 o = make_float2(acc[rb][j][0] * d0, acc[rb][j][1] * d0);
                    *(float2*)(g_Y + (size_t)row0 * F + col) = o;
                }
                if (row1 < n) {
                    float2 o = make_float2(acc[rb][j][2] * d1, acc[rb][j][3] * d1);
                    *(float2*)(g_Y + (size_t)row1 * F + col) = o;
                }
            }
        }
    }
}

// ---------------- aggregation: out[i] = dinv[i]*(Y[i] + sum Y[src]) + b ----
// 8-way unrolled gather, 8 independent accumulators (MLP~8).
template <int F>
__global__ __launch_bounds__(256)
void agg_k(const float* __restrict__ bias, float* __restrict__ out, int n) {
    const int L = F / 4;
    int lane = threadIdx.x & (L - 1);
    int node = (blockIdx.x * blockDim.x + threadIdx.x) / L;
    if (node >= n) return;

    unsigned mask;
    if (L == 32) mask = 0xffffffffu;
    else         mask = 0xffffu << (((threadIdx.x & 31) >> 4) << 4);

    int s = g_rowptr[node];
    int e = g_rowptr[node + 1];

    float4 a[8];
    a[0] = *(const float4*)(g_Y + (size_t)node * F + lane * 4);  // self loop
    #pragma unroll
    for (int q = 1; q < 8; q++) a[q] = make_float4(0.f, 0.f, 0.f, 0.f);

    for (int base = s; base < e; base += L) {
        int idx = base + lane;
        int v = (idx < e) ? g_csrc[idx] : 0;
        int cnt = min(L, e - base);
        int tt = 0;
        for (; tt + 8 <= cnt; tt += 8) {
            int sc[8];
            #pragma unroll
            for (int q = 0; q < 8; q++) sc[q] = __shfl_sync(mask, v, tt + q, L);
            float4 yv[8];
            #pragma unroll
            for (int q = 0; q < 8; q++)
                yv[q] = *(const float4*)(g_Y + (size_t)sc[q] * F + lane * 4);
            #pragma unroll
            for (int q = 0; q < 8; q++) {
                a[q].x += yv[q].x; a[q].y += yv[q].y;
                a[q].z += yv[q].z; a[q].w += yv[q].w;
            }
        }
        for (; tt + 4 <= cnt; tt += 4) {
            int s0 = __shfl_sync(mask, v, tt,     L);
            int s1 = __shfl_sync(mask, v, tt + 1, L);
            int s2 = __shfl_sync(mask, v, tt + 2, L);
            int s3 = __shfl_sync(mask, v, tt + 3, L);
            float4 y0 = *(const float4*)(g_Y + (size_t)s0 * F + lane * 4);
            float4 y1 = *(const float4*)(g_Y + (size_t)s1 * F + lane * 4);
            float4 y2 = *(const float4*)(g_Y + (size_t)s2 * F + lane * 4);
            float4 y3 = *(const float4*)(g_Y + (size_t)s3 * F + lane * 4);
            a[0].x += y0.x; a[0].y += y0.y; a[0].z += y0.z; a[0].w += y0.w;
            a[1].x += y1.x; a[1].y += y1.y; a[1].z += y1.z; a[1].w += y1.w;
            a[2].x += y2.x; a[2].y += y2.y; a[2].z += y2.z; a[2].w += y2.w;
            a[3].x += y3.x; a[3].y += y3.y; a[3].z += y3.z; a[3].w += y3.w;
        }
        for (; tt < cnt; tt++) {
            int sc = __shfl_sync(mask, v, tt, L);
            float4 yv = *(const float4*)(g_Y + (size_t)sc * F + lane * 4);
            a[0].x += yv.x; a[0].y += yv.y; a[0].z += yv.z; a[0].w += yv.w;
        }
    }

    float4 acc;
    acc.x = ((a[0].x + a[1].x) + (a[2].x + a[3].x)) + ((a[4].x + a[5].x) + (a[6].x + a[7].x));
    acc.y = ((a[0].y + a[1].y) + (a[2].y + a[3].y)) + ((a[4].y + a[5].y) + (a[6].y + a[7].y));
    acc.z = ((a[0].z + a[1].z) + (a[2].z + a[3].z)) + ((a[4].z + a[5].z) + (a[6].z + a[7].z));
    acc.w = ((a[0].w + a[1].w) + (a[2].w + a[3].w)) + ((a[4].w + a[5].w) + (a[6].w + a[7].w));

    float d = g_dinv[node];
    float4 bb = *(const float4*)(bias + lane * 4);
    float4 o;
    o.x = fmaf(acc.x, d, bb.x);
    o.y = fmaf(acc.y, d, bb.y);
    o.z = fmaf(acc.z, d, bb.z);
    o.w = fmaf(acc.w, d, bb.w);
    *(float4*)(out + (size_t)node * F + lane * 4) = o;
}

// ---------------- launch -----------------------------------------------------

extern "C" void kernel_launch(void* const* d_in, const int* in_sizes, int n_in,
                              void* d_out, int out_size) {
    const float* x  = (const float*)d_in[0];
    const int*   ei = (const int*)d_in[1];   // int32
    const float* W1 = (const float*)d_in[2];
    const float* b1 = (const float*)d_in[3];
    const float* W2 = (const float*)d_in[4];
    const float* b2 = (const float*)d_in[5];
    const float* W3 = (const float*)d_in[6];
    const float* b3 = (const float*)d_in[7];
    float* out = (float*)d_out;

    float* hH = nullptr;
    cudaGetSymbolAddress((void**)&hH, g_H);
    __nv_bfloat16 *w1h, *w1l, *w2h, *w2l, *w3h, *w3l;
    cudaGetSymbolAddress((void**)&w1h, g_W1h);
    cudaGetSymbolAddress((void**)&w1l, g_W1l);
    cudaGetSymbolAddress((void**)&w2h, g_W2h);
    cudaGetSymbolAddress((void**)&w2l, g_W2l);
    cudaGetSymbolAddress((void**)&w3h, g_W3h);
    cudaGetSymbolAddress((void**)&w3l, g_W3l);

    int n = in_sizes[0] / 128;
    int E = in_sizes[1] / 2;

    const int SMEM128 = 4 * KPAD * (128 + 128);  // 139264 B
    const int SMEM64  = 4 * KPAD * (64  + 128);  // 104448 B
    cudaFuncSetAttribute(gemm_tc<128, false>, cudaFuncAttributeMaxDynamicSharedMemorySize, SMEM128);
    cudaFuncSetAttribute(gemm_tc<128, true>,  cudaFuncAttributeMaxDynamicSharedMemorySize, SMEM128);
    cudaFuncSetAttribute(gemm_tc<64,  true>,  cudaFuncAttributeMaxDynamicSharedMemorySize, SMEM64);

    int nbE4 = (E / 4 + 255) / 256;         // 4 edges per thread
    int nbS  = (n + 1023) / 1024;           // 49 <= 64

    // --- CSR build + weight conversion: 4 kernels ---
    count_k<<<nbE4, 256>>>(ei, E);
    scanconv_k<<<nbS + CONVB, 1024>>>(n, nbS, W1, W2, W3);
    scan_final_k<<<nbS, 1024>>>(n, nbS);
    fill_k<<<nbE4, 256>>>(ei, E);

    int gAgg128 = ((n * 32) + 255) / 256;
    int gAgg64  = ((n * 16) + 255) / 256;

    // --- layer 1 ---
    gemm_tc<128, false><<<148, 256, SMEM128>>>(x, w1h, w1l, n);
    agg_k<128><<<gAgg128, 256>>>(b1, hH, n);

    // --- layer 2 ---
    gemm_tc<128, true><<<148, 256, SMEM128>>>(hH, w2h, w2l, n);
    agg_k<128><<<gAgg128, 256>>>(b2, hH, n);

    // --- layer 3 ---
    gemm_tc<64, true><<<148, 256, SMEM64>>>(hH, w3h, w3l, n);
    agg_k<64><<<gAgg64, 256>>>(b3, out, n);
}

// round 8
// speedup vs baseline: 1.1700x; 1.1700x over previous
#include <cuda_runtime.h>
#include <cuda_bf16.h>
#include <cstdint>

#define NN 50000
#define EE 800000
#define KPAD 136   // bf16 elems per SMEM row (272B) -> conflict-free fragments

// ---------------- scratch (static device globals) --------------------------
__device__ float g_Y[NN * 128];    // post-GEMM features (UNscaled)
__device__ float g_H[NN * 128];    // layer output (post-bias)
__device__ float g_dinv[NN];
__device__ int   g_deg[NN];        // edge-only degree; zeroed by scan_final for next replay
__device__ int   g_cursor[NN];
__device__ int   g_rowptr[NN + 1];
__device__ int   g_csrc[EE];
__device__ int   g_bsum[64];
// pre-split, pre-transposed weights: [N][K=128] bf16, hi + lo parts
__device__ __nv_bfloat16 g_W1h[128 * 128], g_W1l[128 * 128];
__device__ __nv_bfloat16 g_W2h[128 * 128], g_W2l[128 * 128];
__device__ __nv_bfloat16 g_W3h[64 * 128],  g_W3l[64 * 128];

// ---------------- preprocessing (stream B) -----------------------------------

__global__ void count_k(const int* __restrict__ ei, int E) {
    int e = blockIdx.x * blockDim.x + threadIdx.x;
    if (e < E) atomicAdd(&g_deg[ei[E + e]], 1);
}

// dinv + per-1024-chunk partial sums of edge-degree
__global__ void scan_partial_k(int n) {
    __shared__ int sm[32];
    int tid = threadIdx.x;
    int i = blockIdx.x * 1024 + tid;
    int v = 0;
    if (i < n) {
        v = g_deg[i];                       // edge-only degree
        g_dinv[i] = rsqrtf((float)(v + 1)); // +1 self-loop
    }
    int vv = v;
    #pragma unroll
    for (int o = 16; o > 0; o >>= 1) vv += __shfl_down_sync(0xffffffffu, vv, o);
    int lane = tid & 31, wid = tid >> 5;
    if (lane == 0) sm[wid] = vv;
    __syncthreads();
    if (wid == 0) {
        vv = sm[lane];
        #pragma unroll
        for (int o = 16; o > 0; o >>= 1) vv += __shfl_down_sync(0xffffffffu, vv, o);
        if (lane == 0) g_bsum[blockIdx.x] = vv;
    }
}

// rowptr + cursor + zero deg; each block computes its own bsum-prefix (nbS<=64)
__global__ void scan_final_k(int n, int nbS) {
    __shared__ int sm[1024];
    __shared__ int s_off;
    int tid = threadIdx.x;
    int bid = blockIdx.x;
    int i = bid * 1024 + tid;

    if (tid < 32) {
        int a = (tid      < bid) ? g_bsum[tid]      : 0;
        int b = (tid + 32 < bid) ? g_bsum[tid + 32] : 0;
        int s = a + b;
        #pragma unroll
        for (int o = 16; o > 0; o >>= 1) s += __shfl_down_sync(0xffffffffu, s, o);
        if (tid == 0) s_off = s;
    }

    int v = 0;
    if (i < n) {
        v = g_deg[i];
        g_deg[i] = 0;                        // reset for next graph replay
    }
    sm[tid] = v;
    __syncthreads();
    #pragma unroll
    for (int off = 1; off < 1024; off <<= 1) {
        int t = 0;
        if (tid >= off) t = sm[tid - off];
        __syncthreads();
        if (tid >= off) sm[tid] += t;
        __syncthreads();
    }
    int incl = sm[tid];
    if (i < n) {
        int rp = s_off + incl - v;
        g_rowptr[i] = rp;
        g_cursor[i] = rp;
        if (i == n - 1) g_rowptr[n] = s_off + incl;
    }
}

__global__ void fill_k(const int* __restrict__ ei, int E) {
    int e = blockIdx.x * blockDim.x + threadIdx.x;
    if (e < E) {
        int s = ei[e];
        int d = ei[E + e];
        int pos = atomicAdd(&g_cursor[d], 1);
        g_csrc[pos] = s;
    }
}

// ---------------- weight conversion (main stream, before gemm1) -------------
__device__ __forceinline__ void conv_one(const float* W, __nv_bfloat16* Wh,
                                         __nv_bfloat16* Wl, int F, int idx) {
    int nn = idx >> 7, k = idx & 127;
    float v = W[k * F + nn];
    __nv_bfloat16 h = __float2bfloat16(v);
    __nv_bfloat16 l = __float2bfloat16(v - __bfloat162float(h));
    Wh[nn * 128 + k] = h;
    Wl[nn * 128 + k] = l;
}

__global__ void convW_all_k(const float* __restrict__ W1,
                            const float* __restrict__ W2,
                            const float* __restrict__ W3) {
    int idx = blockIdx.x * blockDim.x + threadIdx.x;
    if (idx < 16384)       conv_one(W1, g_W1h, g_W1l, 128, idx);
    else if (idx < 32768)  conv_one(W2, g_W2h, g_W2l, 128, idx - 16384);
    else if (idx < 40960)  conv_one(W3, g_W3h, g_W3l, 64,  idx - 32768);
}

// ---------------- tensor-core GEMM ------------------------------------------
// Y[n,F] = relu?(A[n,128]) @ W[128,F]   (no dinv scaling; done in agg)

__device__ __forceinline__ unsigned packbf(float a, float b) {
    __nv_bfloat162 p = __floats2bfloat162_rn(a, b);
    return *reinterpret_cast<unsigned*>(&p);
}

__device__ __forceinline__ void mma_bf16(float* c,
                                         unsigned a0, unsigned a1, unsigned a2, unsigned a3,
                                         unsigned b0, unsigned b1) {
    asm volatile(
        "mma.sync.aligned.m16n8k16.row.col.f32.bf16.bf16.f32 "
        "{%0,%1,%2,%3}, {%4,%5,%6,%7}, {%8,%9}, {%0,%1,%2,%3};"
        : "+f"(c[0]), "+f"(c[1]), "+f"(c[2]), "+f"(c[3])
        : "r"(a0), "r"(a1), "r"(a2), "r"(a3), "r"(b0), "r"(b1));
}

template <int F, bool RELU>
__global__ __launch_bounds__(256)
void gemm_tc(const float* __restrict__ A,
             const __nv_bfloat16* __restrict__ Wh,
             const __nv_bfloat16* __restrict__ Wl, int n) {
    extern __shared__ unsigned char smraw[];
    __nv_bfloat16* sWh = (__nv_bfloat16*)smraw;        // F * KPAD
    __nv_bfloat16* sWl = sWh + F * KPAD;
    __nv_bfloat16* sAh = sWl + F * KPAD;               // 128 * KPAD
    __nv_bfloat16* sAl = sAh + 128 * KPAD;

    const int NT = F / 16;
    int tid = threadIdx.x;
    int wid = tid >> 5, lane = tid & 31;
    int g = lane >> 2, t = lane & 3;
    int wm = wid >> 1;
    int wn = wid & 1;
    int arow = wm * 32;
    int bcol0 = wn * (F / 2);

    {
        const unsigned* gwh = (const unsigned*)Wh;
        const unsigned* gwl = (const unsigned*)Wl;
        for (int i = tid; i < F * 64; i += 256) {
            int r = i >> 6, c = i & 63;
            ((unsigned*)(sWh + r * KPAD))[c] = gwh[i];
            ((unsigned*)(sWl + r * KPAD))[c] = gwl[i];
        }
    }

    int ntiles = (n + 127) >> 7;
    for (int tile = blockIdx.x; tile < ntiles; tile += gridDim.x) {
        __syncthreads();
        int r0 = tile * 128;

        for (int i = tid; i < 4096; i += 256) {
            int r = i >> 5, c4 = i & 31;
            int row = r0 + r;
            float4 v = make_float4(0.f, 0.f, 0.f, 0.f);
            if (row < n) v = *(const float4*)(A + (size_t)row * 128 + c4 * 4);
            if (RELU) {
                v.x = fmaxf(v.x, 0.f); v.y = fmaxf(v.y, 0.f);
                v.z = fmaxf(v.z, 0.f); v.w = fmaxf(v.w, 0.f);
            }
            __nv_bfloat16 h0 = __float2bfloat16(v.x), h1 = __float2bfloat16(v.y);
            __nv_bfloat16 h2 = __float2bfloat16(v.z), h3 = __float2bfloat16(v.w);
            float l0 = v.x - __bfloat162float(h0), l1 = v.y - __bfloat162float(h1);
            float l2 = v.z - __bfloat162float(h2), l3 = v.w - __bfloat162float(h3);
            unsigned h01, h23;
            { __nv_bfloat162 p0 = {h0, h1}; h01 = *reinterpret_cast<unsigned*>(&p0);
              __nv_bfloat162 p1 = {h2, h3}; h23 = *reinterpret_cast<unsigned*>(&p1); }
            unsigned l01 = packbf(l0, l1), l23 = packbf(l2, l3);
            *reinterpret_cast<uint2*>(sAh + r * KPAD + c4 * 4) = make_uint2(h01, h23);
            *reinterpret_cast<uint2*>(sAl + r * KPAD + c4 * 4) = make_uint2(l01, l23);
        }
        __syncthreads();

        float acc[2][NT][4];
        #pragma unroll
        for (int rb = 0; rb < 2; rb++)
            #pragma unroll
            for (int j = 0; j < NT; j++) {
                acc[rb][j][0] = 0.f; acc[rb][j][1] = 0.f;
                acc[rb][j][2] = 0.f; acc[rb][j][3] = 0.f;
            }

        #pragma unroll
        for (int kk = 0; kk < 128; kk += 16) {
            unsigned ah[2][4], al[2][4];
            #pragma unroll
            for (int rb = 0; rb < 2; rb++) {
                int br = arow + rb * 16;
                ah[rb][0] = *(const unsigned*)(sAh + (br + g)     * KPAD + kk + 2 * t);
                ah[rb][1] = *(const unsigned*)(sAh + (br + g + 8) * KPAD + kk + 2 * t);
                ah[rb][2] = *(const unsigned*)(sAh + (br + g)     * KPAD + kk + 8 + 2 * t);
                ah[rb][3] = *(const unsigned*)(sAh + (br + g + 8) * KPAD + kk + 8 + 2 * t);
                al[rb][0] = *(const unsigned*)(sAl + (br + g)     * KPAD + kk + 2 * t);
                al[rb][1] = *(const unsigned*)(sAl + (br + g + 8) * KPAD + kk + 2 * t);
                al[rb][2] = *(const unsigned*)(sAl + (br + g)     * KPAD + kk + 8 + 2 * t);
                al[rb][3] = *(const unsigned*)(sAl + (br + g + 8) * KPAD + kk + 8 + 2 * t);
            }
            #pragma unroll
            for (int j = 0; j < NT; j++) {
                int bn = bcol0 + j * 8 + g;
                unsigned b0h = *(const unsigned*)(sWh + bn * KPAD + kk + 2 * t);
                unsigned b1h = *(const unsigned*)(sWh + bn * KPAD + kk + 8 + 2 * t);
                unsigned b0l = *(const unsigned*)(sWl + bn * KPAD + kk + 2 * t);
                unsigned b1l = *(const unsigned*)(sWl + bn * KPAD + kk + 8 + 2 * t);
                #pragma unroll
                for (int rb = 0; rb < 2; rb++) {
                    mma_bf16(acc[rb][j], ah[rb][0], ah[rb][1], ah[rb][2], ah[rb][3], b0h, b1h);
                    mma_bf16(acc[rb][j], ah[rb][0], ah[rb][1], ah[rb][2], ah[rb][3], b0l, b1l);
                    mma_bf16(acc[rb][j], al[rb][0], al[rb][1], al[rb][2], al[rb][3], b0h, b1h);
                }
            }
        }

        #pragma unroll
        for (int rb = 0; rb < 2; rb++) {
            int row0 = r0 + arow + rb * 16 + g;
            int row1 = row0 + 8;
            #pragma unroll
            for (int j = 0; j < NT; j++) {
                int col = bcol0 + j * 8 + 2 * t;
                if (row0 < n) {
                    float2 o = make_float2(acc[rb][j][0], acc[rb][j][1]);
                    *(float2*)(g_Y + (size_t)row0 * F + col) = o;
                }
                if (row1 < n) {
                    float2 o = make_float2(acc[rb][j][2], acc[rb][j][3]);
                    *(float2*)(g_Y + (size_t)row1 * F + col) = o;
                }
            }
        }
    }
}

// ---------------- aggregation ------------------------------------------------
// out[i] = dinv[i]*( dinv[i]*Y[i] + sum_s dinv[s]*Y[s] ) + b
template <int F>
__global__ __launch_bounds__(256)
void agg_k(const float* __restrict__ bias, float* __restrict__ out, int n) {
    const int L = F / 4;
    int lane = threadIdx.x & (L - 1);
    int node = (blockIdx.x * blockDim.x + threadIdx.x) / L;
    if (node >= n) return;

    unsigned mask;
    if (L == 32) mask = 0xffffffffu;
    else         mask = 0xffffu << (((threadIdx.x & 31) >> 4) << 4);

    int s = g_rowptr[node];
    int e = g_rowptr[node + 1];
    float di = g_dinv[node];

    float4 self = *(const float4*)(g_Y + (size_t)node * F + lane * 4);
    float4 a0, a1, a2, a3;
    a0.x = self.x * di; a0.y = self.y * di; a0.z = self.z * di; a0.w = self.w * di;
    a1 = make_float4(0.f, 0.f, 0.f, 0.f);
    a2 = make_float4(0.f, 0.f, 0.f, 0.f);
    a3 = make_float4(0.f, 0.f, 0.f, 0.f);

    for (int base = s; base < e; base += L) {
        int idx = base + lane;
        int v = (idx < e) ? g_csrc[idx] : 0;
        int cnt = min(L, e - base);
        int tt = 0;
        for (; tt + 4 <= cnt; tt += 4) {
            int s0 = __shfl_sync(mask, v, tt,     L);
            int s1 = __shfl_sync(mask, v, tt + 1, L);
            int s2 = __shfl_sync(mask, v, tt + 2, L);
            int s3 = __shfl_sync(mask, v, tt + 3, L);
            float d0 = g_dinv[s0], d1 = g_dinv[s1], d2 = g_dinv[s2], d3 = g_dinv[s3];
            float4 y0 = *(const float4*)(g_Y + (size_t)s0 * F + lane * 4);
            float4 y1 = *(const float4*)(g_Y + (size_t)s1 * F + lane * 4);
            float4 y2 = *(const float4*)(g_Y + (size_t)s2 * F + lane * 4);
            float4 y3 = *(const float4*)(g_Y + (size_t)s3 * F + lane * 4);
            a0.x = fmaf(y0.x, d0, a0.x); a0.y = fmaf(y0.y, d0, a0.y);
            a0.z = fmaf(y0.z, d0, a0.z); a0.w = fmaf(y0.w, d0, a0.w);
            a1.x = fmaf(y1.x, d1, a1.x); a1.y = fmaf(y1.y, d1, a1.y);
            a1.z = fmaf(y1.z, d1, a1.z); a1.w = fmaf(y1.w, d1, a1.w);
            a2.x = fmaf(y2.x, d2, a2.x); a2.y = fmaf(y2.y, d2, a2.y);
            a2.z = fmaf(y2.z, d2, a2.z); a2.w = fmaf(y2.w, d2, a2.w);
            a3.x = fmaf(y3.x, d3, a3.x); a3.y = fmaf(y3.y, d3, a3.y);
            a3.z = fmaf(y3.z, d3, a3.z); a3.w = fmaf(y3.w, d3, a3.w);
        }
        for (; tt < cnt; tt++) {
            int sc = __shfl_sync(mask, v, tt, L);
            float dd = g_dinv[sc];
            float4 yv = *(const float4*)(g_Y + (size_t)sc * F + lane * 4);
            a0.x = fmaf(yv.x, dd, a0.x); a0.y = fmaf(yv.y, dd, a0.y);
            a0.z = fmaf(yv.z, dd, a0.z); a0.w = fmaf(yv.w, dd, a0.w);
        }
    }

    float4 acc;
    acc.x = (a0.x + a1.x) + (a2.x + a3.x);
    acc.y = (a0.y + a1.y) + (a2.y + a3.y);
    acc.z = (a0.z + a1.z) + (a2.z + a3.z);
    acc.w = (a0.w + a1.w) + (a2.w + a3.w);

    float4 bb = *(const float4*)(bias + lane * 4);
    float4 o;
    o.x = fmaf(acc.x, di, bb.x);
    o.y = fmaf(acc.y, di, bb.y);
    o.z = fmaf(acc.z, di, bb.z);
    o.w = fmaf(acc.w, di, bb.w);
    *(float4*)(out + (size_t)node * F + lane * 4) = o;
}

// ---------------- launch -----------------------------------------------------

extern "C" void kernel_launch(void* const* d_in, const int* in_sizes, int n_in,
                              void* d_out, int out_size) {
    const float* x  = (const float*)d_in[0];
    const int*   ei = (const int*)d_in[1];   // int32
    const float* W1 = (const float*)d_in[2];
    const float* b1 = (const float*)d_in[3];
    const float* W2 = (const float*)d_in[4];
    const float* b2 = (const float*)d_in[5];
    const float* W3 = (const float*)d_in[6];
    const float* b3 = (const float*)d_in[7];
    float* out = (float*)d_out;

    float* hH = nullptr;
    cudaGetSymbolAddress((void**)&hH, g_H);
    __nv_bfloat16 *w1h, *w1l, *w2h, *w2l, *w3h, *w3l;
    cudaGetSymbolAddress((void**)&w1h, g_W1h);
    cudaGetSymbolAddress((void**)&w1l, g_W1l);
    cudaGetSymbolAddress((void**)&w2h, g_W2h);
    cudaGetSymbolAddress((void**)&w2l, g_W2l);
    cudaGetSymbolAddress((void**)&w3h, g_W3h);
    cudaGetSymbolAddress((void**)&w3l, g_W3l);

    int n = in_sizes[0] / 128;
    int E = in_sizes[1] / 2;

    const int SMEM128 = 4 * KPAD * (128 + 128);  // 139264 B
    const int SMEM64  = 4 * KPAD * (64  + 128);  // 104448 B
    cudaFuncSetAttribute(gemm_tc<128, false>, cudaFuncAttributeMaxDynamicSharedMemorySize, SMEM128);
    cudaFuncSetAttribute(gemm_tc<128, true>,  cudaFuncAttributeMaxDynamicSharedMemorySize, SMEM128);
    cudaFuncSetAttribute(gemm_tc<64,  true>,  cudaFuncAttributeMaxDynamicSharedMemorySize, SMEM64);

    // side stream + fork/join events (created once, on the un-captured
    // correctness call; reused identically every call -> deterministic work)
    static cudaStream_t sB = nullptr;
    static cudaEvent_t  evF = nullptr, evJ = nullptr;
    if (sB == nullptr) {
        cudaStreamCreateWithFlags(&sB, cudaStreamNonBlocking);
        cudaEventCreateWithFlags(&evF, cudaEventDisableTiming);
        cudaEventCreateWithFlags(&evJ, cudaEventDisableTiming);
    }

    int nbE = (E + 255) / 256;
    int nbS = (n + 1023) / 1024;   // 49 <= 64

    // ---- fork: CSR build on stream B, convW+gemm1 on main stream ----
    cudaEventRecord(evF, 0);
    cudaStreamWaitEvent(sB, evF, 0);

    count_k<<<nbE, 256, 0, sB>>>(ei, E);
    scan_partial_k<<<nbS, 1024, 0, sB>>>(n);
    scan_final_k<<<nbS, 1024, 0, sB>>>(n, nbS);
    fill_k<<<nbE, 256, 0, sB>>>(ei, E);
    cudaEventRecord(evJ, sB);

    convW_all_k<<<160, 256>>>(W1, W2, W3);
    gemm_tc<128, false><<<148, 256, SMEM128>>>(x, w1h, w1l, n);

    // ---- join: everything after needs CSR + dinv ----
    cudaStreamWaitEvent(0, evJ, 0);

    int gAgg128 = ((n * 32) + 255) / 256;
    int gAgg64  = ((n * 16) + 255) / 256;

    agg_k<128><<<gAgg128, 256>>>(b1, hH, n);

    gemm_tc<128, true><<<148, 256, SMEM128>>>(hH, w2h, w2l, n);
    agg_k<128><<<gAgg128, 256>>>(b2, hH, n);

    gemm_tc<64, true><<<148, 256, SMEM64>>>(hH, w3h, w3l, n);
    agg_k<64><<<gAgg64, 256>>>(b3, out, n);
}

// round 9
// speedup vs baseline: 1.2218x; 1.0443x over previous
#include <cuda_runtime.h>
#include <cuda_bf16.h>
#include <cstdint>

#define NN 50000
#define EE 800000
#define KPAD 136   // bf16 elems per SMEM row (272B) -> conflict-free fragments

// ---------------- scratch (static device globals) --------------------------
__device__ float g_Y[NN * 128];    // post-GEMM, dinv[row]-scaled features
__device__ float g_H[NN * 128];    // layer output (post-bias)
__device__ float g_dinv[NN];
__device__ int   g_deg[NN];        // edge-only degree; zeroed by scan_final for next replay
__device__ int   g_cursor[NN];
__device__ int   g_rowptr[NN + 1];
__device__ int   g_csrc[EE];
__device__ int   g_bsum[64];
// pre-split, pre-transposed weights: [N][K=128] bf16, hi + lo parts
__device__ __nv_bfloat16 g_W1h[128 * 128], g_W1l[128 * 128];
__device__ __nv_bfloat16 g_W2h[128 * 128], g_W2l[128 * 128];
__device__ __nv_bfloat16 g_W3h[64 * 128],  g_W3l[64 * 128];

// ---------------- preprocessing (main stream) --------------------------------

__global__ void count_k(const int* __restrict__ ei, int E) {
    int e = blockIdx.x * blockDim.x + threadIdx.x;
    if (e < E) atomicAdd(&g_deg[ei[E + e]], 1);
}

// dinv + per-1024-chunk partial sums of edge-degree
__global__ void scan_partial_k(int n) {
    __shared__ int sm[32];
    int tid = threadIdx.x;
    int i = blockIdx.x * 1024 + tid;
    int v = 0;
    if (i < n) {
        v = g_deg[i];                       // edge-only degree
        g_dinv[i] = rsqrtf((float)(v + 1)); // +1 self-loop
    }
    int vv = v;
    #pragma unroll
    for (int o = 16; o > 0; o >>= 1) vv += __shfl_down_sync(0xffffffffu, vv, o);
    int lane = tid & 31, wid = tid >> 5;
    if (lane == 0) sm[wid] = vv;
    __syncthreads();
    if (wid == 0) {
        vv = sm[lane];
        #pragma unroll
        for (int o = 16; o > 0; o >>= 1) vv += __shfl_down_sync(0xffffffffu, vv, o);
        if (lane == 0) g_bsum[blockIdx.x] = vv;
    }
}

// rowptr + cursor + zero deg; each block computes its own bsum-prefix (nbS<=64)
__global__ void scan_final_k(int n, int nbS) {
    __shared__ int sm[1024];
    __shared__ int s_off;
    int tid = threadIdx.x;
    int bid = blockIdx.x;
    int i = bid * 1024 + tid;

    if (tid < 32) {
        int a = (tid      < bid) ? g_bsum[tid]      : 0;
        int b = (tid + 32 < bid) ? g_bsum[tid + 32] : 0;
        int s = a + b;
        #pragma unroll
        for (int o = 16; o > 0; o >>= 1) s += __shfl_down_sync(0xffffffffu, s, o);
        if (tid == 0) s_off = s;
    }

    int v = 0;
    if (i < n) {
        v = g_deg[i];
        g_deg[i] = 0;                        // reset for next graph replay
    }
    sm[tid] = v;
    __syncthreads();
    #pragma unroll
    for (int off = 1; off < 1024; off <<= 1) {
        int t = 0;
        if (tid >= off) t = sm[tid - off];
        __syncthreads();
        if (tid >= off) sm[tid] += t;
        __syncthreads();
    }
    int incl = sm[tid];
    if (i < n) {
        int rp = s_off + incl - v;
        g_rowptr[i] = rp;
        g_cursor[i] = rp;
        if (i == n - 1) g_rowptr[n] = s_off + incl;
    }
}

__global__ void fill_k(const int* __restrict__ ei, int E) {
    int e = blockIdx.x * blockDim.x + threadIdx.x;
    if (e < E) {
        int s = ei[e];
        int d = ei[E + e];
        int pos = atomicAdd(&g_cursor[d], 1);
        g_csrc[pos] = s;
    }
}

// ---------------- weight conversion (stream B) -------------------------------
__device__ __forceinline__ void conv_one(const float* W, __nv_bfloat16* Wh,
                                         __nv_bfloat16* Wl, int F, int idx) {
    int nn = idx >> 7, k = idx & 127;
    float v = W[k * F + nn];
    __nv_bfloat16 h = __float2bfloat16(v);
    __nv_bfloat16 l = __float2bfloat16(v - __bfloat162float(h));
    Wh[nn * 128 + k] = h;
    Wl[nn * 128 + k] = l;
}

__global__ void convW_all_k(const float* __restrict__ W1,
                            const float* __restrict__ W2,
                            const float* __restrict__ W3) {
    int idx = blockIdx.x * blockDim.x + threadIdx.x;
    if (idx < 16384)       conv_one(W1, g_W1h, g_W1l, 128, idx);
    else if (idx < 32768)  conv_one(W2, g_W2h, g_W2l, 128, idx - 16384);
    else if (idx < 40960)  conv_one(W3, g_W3h, g_W3l, 64,  idx - 32768);
}

// ---------------- tensor-core GEMM ------------------------------------------
// Y[n,F] = (relu?(A[n,128]) @ W[128,F]) * dinv[row],  bf16x3 split for fp32.

__device__ __forceinline__ unsigned packbf(float a, float b) {
    __nv_bfloat162 p = __floats2bfloat162_rn(a, b);
    return *reinterpret_cast<unsigned*>(&p);
}

__device__ __forceinline__ void mma_bf16(float* c,
                                         unsigned a0, unsigned a1, unsigned a2, unsigned a3,
                                         unsigned b0, unsigned b1) {
    asm volatile(
        "mma.sync.aligned.m16n8k16.row.col.f32.bf16.bf16.f32 "
        "{%0,%1,%2,%3}, {%4,%5,%6,%7}, {%8,%9}, {%0,%1,%2,%3};"
        : "+f"(c[0]), "+f"(c[1]), "+f"(c[2]), "+f"(c[3])
        : "r"(a0), "r"(a1), "r"(a2), "r"(a3), "r"(b0), "r"(b1));
}

template <int F, bool RELU>
__global__ __launch_bounds__(256)
void gemm_tc(const float* __restrict__ A,
             const __nv_bfloat16* __restrict__ Wh,
             const __nv_bfloat16* __restrict__ Wl, int n) {
    extern __shared__ unsigned char smraw[];
    __nv_bfloat16* sWh = (__nv_bfloat16*)smraw;        // F * KPAD
    __nv_bfloat16* sWl = sWh + F * KPAD;
    __nv_bfloat16* sAh = sWl + F * KPAD;               // 128 * KPAD
    __nv_bfloat16* sAl = sAh + 128 * KPAD;

    const int NT = F / 16;
    int tid = threadIdx.x;
    int wid = tid >> 5, lane = tid & 31;
    int g = lane >> 2, t = lane & 3;
    int wm = wid >> 1;
    int wn = wid & 1;
    int arow = wm * 32;
    int bcol0 = wn * (F / 2);

    {
        const unsigned* gwh = (const unsigned*)Wh;
        const unsigned* gwl = (const unsigned*)Wl;
        for (int i = tid; i < F * 64; i += 256) {
            int r = i >> 6, c = i & 63;
            ((unsigned*)(sWh + r * KPAD))[c] = gwh[i];
            ((unsigned*)(sWl + r * KPAD))[c] = gwl[i];
        }
    }

    int ntiles = (n + 127) >> 7;
    for (int tile = blockIdx.x; tile < ntiles; tile += gridDim.x) {
        __syncthreads();
        int r0 = tile * 128;

        for (int i = tid; i < 4096; i += 256) {
            int r = i >> 5, c4 = i & 31;
            int row = r0 + r;
            float4 v = make_float4(0.f, 0.f, 0.f, 0.f);
            if (row < n) v = *(const float4*)(A + (size_t)row * 128 + c4 * 4);
            if (RELU) {
                v.x = fmaxf(v.x, 0.f); v.y = fmaxf(v.y, 0.f);
                v.z = fmaxf(v.z, 0.f); v.w = fmaxf(v.w, 0.f);
            }
            __nv_bfloat16 h0 = __float2bfloat16(v.x), h1 = __float2bfloat16(v.y);
            __nv_bfloat16 h2 = __float2bfloat16(v.z), h3 = __float2bfloat16(v.w);
            float l0 = v.x - __bfloat162float(h0), l1 = v.y - __bfloat162float(h1);
            float l2 = v.z - __bfloat162float(h2), l3 = v.w - __bfloat162float(h3);
            unsigned h01, h23;
            { __nv_bfloat162 p0 = {h0, h1}; h01 = *reinterpret_cast<unsigned*>(&p0);
              __nv_bfloat162 p1 = {h2, h3}; h23 = *reinterpret_cast<unsigned*>(&p1); }
            unsigned l01 = packbf(l0, l1), l23 = packbf(l2, l3);
            *reinterpret_cast<uint2*>(sAh + r * KPAD + c4 * 4) = make_uint2(h01, h23);
            *reinterpret_cast<uint2*>(sAl + r * KPAD + c4 * 4) = make_uint2(l01, l23);
        }
        __syncthreads();

        float acc[2][NT][4];
        #pragma unroll
        for (int rb = 0; rb < 2; rb++)
            #pragma unroll
            for (int j = 0; j < NT; j++) {
                acc[rb][j][0] = 0.f; acc[rb][j][1] = 0.f;
                acc[rb][j][2] = 0.f; acc[rb][j][3] = 0.f;
            }

        #pragma unroll
        for (int kk = 0; kk < 128; kk += 16) {
            unsigned ah[2][4], al[2][4];
            #pragma unroll
            for (int rb = 0; rb < 2; rb++) {
                int br = arow + rb * 16;
                ah[rb][0] = *(const unsigned*)(sAh + (br + g)     * KPAD + kk + 2 * t);
                ah[rb][1] = *(const unsigned*)(sAh + (br + g + 8) * KPAD + kk + 2 * t);
                ah[rb][2] = *(const unsigned*)(sAh + (br + g)     * KPAD + kk + 8 + 2 * t);
                ah[rb][3] = *(const unsigned*)(sAh + (br + g + 8) * KPAD + kk + 8 + 2 * t);
                al[rb][0] = *(const unsigned*)(sAl + (br + g)     * KPAD + kk + 2 * t);
                al[rb][1] = *(const unsigned*)(sAl + (br + g + 8) * KPAD + kk + 2 * t);
                al[rb][2] = *(const unsigned*)(sAl + (br + g)     * KPAD + kk + 8 + 2 * t);
                al[rb][3] = *(const unsigned*)(sAl + (br + g + 8) * KPAD + kk + 8 + 2 * t);
            }
            #pragma unroll
            for (int j = 0; j < NT; j++) {
                int bn = bcol0 + j * 8 + g;
                unsigned b0h = *(const unsigned*)(sWh + bn * KPAD + kk + 2 * t);
                unsigned b1h = *(const unsigned*)(sWh + bn * KPAD + kk + 8 + 2 * t);
                unsigned b0l = *(const unsigned*)(sWl + bn * KPAD + kk + 2 * t);
                unsigned b1l = *(const unsigned*)(sWl + bn * KPAD + kk + 8 + 2 * t);
                #pragma unroll
                for (int rb = 0; rb < 2; rb++) {
                    mma_bf16(acc[rb][j], ah[rb][0], ah[rb][1], ah[rb][2], ah[rb][3], b0h, b1h);
                    mma_bf16(acc[rb][j], ah[rb][0], ah[rb][1], ah[rb][2], ah[rb][3], b0l, b1l);
                    mma_bf16(acc[rb][j], al[rb][0], al[rb][1], al[rb][2], al[rb][3], b0h, b1h);
                }
            }
        }

        #pragma unroll
        for (int rb = 0; rb < 2; rb++) {
            int row0 = r0 + arow + rb * 16 + g;
            int row1 = row0 + 8;
            float d0 = (row0 < n) ? g_dinv[row0] : 0.f;
            float d1 = (row1 < n) ? g_dinv[row1] : 0.f;
            #pragma unroll
            for (int j = 0; j < NT; j++) {
                int col = bcol0 + j * 8 + 2 * t;
                if (row0 < n) {
                    float2 o = make_float2(acc[rb][j][0] * d0, acc[rb][j][1] * d0);
                    *(float2*)(g_Y + (size_t)row0 * F + col) = o;
                }
                if (row1 < n) {
                    float2 o = make_float2(acc[rb][j][2] * d1, acc[rb][j][3] * d1);
                    *(float2*)(g_Y + (size_t)row1 * F + col) = o;
                }
            }
        }
    }
}

// ---------------- aggregation: out[i] = dinv[i]*(Y[i] + sum Y[src]) + b ----
template <int F>
__global__ __launch_bounds__(256)
void agg_k(const float* __restrict__ bias, float* __restrict__ out, int n) {
    const int L = F / 4;
    int lane = threadIdx.x & (L - 1);
    int node = (blockIdx.x * blockDim.x + threadIdx.x) / L;
    if (node >= n) return;

    unsigned mask;
    if (L == 32) mask = 0xffffffffu;
    else         mask = 0xffffu << (((threadIdx.x & 31) >> 4) << 4);

    int s = g_rowptr[node];
    int e = g_rowptr[node + 1];

    float4 a0 = *(const float4*)(g_Y + (size_t)node * F + lane * 4);  // self loop
    float4 a1 = make_float4(0.f, 0.f, 0.f, 0.f);
    float4 a2 = make_float4(0.f, 0.f, 0.f, 0.f);
    float4 a3 = make_float4(0.f, 0.f, 0.f, 0.f);

    for (int base = s; base < e; base += L) {
        int idx = base + lane;
        int v = (idx < e) ? g_csrc[idx] : 0;
        int cnt = min(L, e - base);
        int tt = 0;
        for (; tt + 4 <= cnt; tt += 4) {
            int s0 = __shfl_sync(mask, v, tt,     L);
            int s1 = __shfl_sync(mask, v, tt + 1, L);
            int s2 = __shfl_sync(mask, v, tt + 2, L);
            int s3 = __shfl_sync(mask, v, tt + 3, L);
            float4 y0 = *(const float4*)(g_Y + (size_t)s0 * F + lane * 4);
            float4 y1 = *(const float4*)(g_Y + (size_t)s1 * F + lane * 4);
            float4 y2 = *(const float4*)(g_Y + (size_t)s2 * F + lane * 4);
            float4 y3 = *(const float4*)(g_Y + (size_t)s3 * F + lane * 4);
            a0.x += y0.x; a0.y += y0.y; a0.z += y0.z; a0.w += y0.w;
            a1.x += y1.x; a1.y += y1.y; a1.z += y1.z; a1.w += y1.w;
            a2.x += y2.x; a2.y += y2.y; a2.z += y2.z; a2.w += y2.w;
            a3.x += y3.x; a3.y += y3.y; a3.z += y3.z; a3.w += y3.w;
        }
        for (; tt < cnt; tt++) {
            int sc = __shfl_sync(mask, v, tt, L);
            float4 yv = *(const float4*)(g_Y + (size_t)sc * F + lane * 4);
            a0.x += yv.x; a0.y += yv.y; a0.z += yv.z; a0.w += yv.w;
        }
    }

    float4 acc;
    acc.x = (a0.x + a1.x) + (a2.x + a3.x);
    acc.y = (a0.y + a1.y) + (a2.y + a3.y);
    acc.z = (a0.z + a1.z) + (a2.z + a3.z);
    acc.w = (a0.w + a1.w) + (a2.w + a3.w);

    float d = g_dinv[node];
    float4 bb = *(const float4*)(bias + lane * 4);
    float4 o;
    o.x = fmaf(acc.x, d, bb.x);
    o.y = fmaf(acc.y, d, bb.y);
    o.z = fmaf(acc.z, d, bb.z);
    o.w = fmaf(acc.w, d, bb.w);
    *(float4*)(out + (size_t)node * F + lane * 4) = o;
}

// ---------------- launch -----------------------------------------------------

extern "C" void kernel_launch(void* const* d_in, const int* in_sizes, int n_in,
                              void* d_out, int out_size) {
    const float* x  = (const float*)d_in[0];
    const int*   ei = (const int*)d_in[1];   // int32
    const float* W1 = (const float*)d_in[2];
    const float* b1 = (const float*)d_in[3];
    const float* W2 = (const float*)d_in[4];
    const float* b2 = (const float*)d_in[5];
    const float* W3 = (const float*)d_in[6];
    const float* b3 = (const float*)d_in[7];
    float* out = (float*)d_out;

    float* hH = nullptr;
    cudaGetSymbolAddress((void**)&hH, g_H);
    __nv_bfloat16 *w1h, *w1l, *w2h, *w2l, *w3h, *w3l;
    cudaGetSymbolAddress((void**)&w1h, g_W1h);
    cudaGetSymbolAddress((void**)&w1l, g_W1l);
    cudaGetSymbolAddress((void**)&w2h, g_W2h);
    cudaGetSymbolAddress((void**)&w2l, g_W2l);
    cudaGetSymbolAddress((void**)&w3h, g_W3h);
    cudaGetSymbolAddress((void**)&w3l, g_W3l);

    int n = in_sizes[0] / 128;
    int E = in_sizes[1] / 2;

    const int SMEM128 = 4 * KPAD * (128 + 128);  // 139264 B
    const int SMEM64  = 4 * KPAD * (64  + 128);  // 104448 B
    cudaFuncSetAttribute(gemm_tc<128, false>, cudaFuncAttributeMaxDynamicSharedMemorySize, SMEM128);
    cudaFuncSetAttribute(gemm_tc<128, true>,  cudaFuncAttributeMaxDynamicSharedMemorySize, SMEM128);
    cudaFuncSetAttribute(gemm_tc<64,  true>,  cudaFuncAttributeMaxDynamicSharedMemorySize, SMEM64);

    // side stream + events (created once on the un-captured correctness call)
    static cudaStream_t sB = nullptr;
    static cudaEvent_t  evF = nullptr, evD = nullptr, evJ = nullptr;
    if (sB == nullptr) {
        cudaStreamCreateWithFlags(&sB, cudaStreamNonBlocking);
        cudaEventCreateWithFlags(&evF, cudaEventDisableTiming);
        cudaEventCreateWithFlags(&evD, cudaEventDisableTiming);
        cudaEventCreateWithFlags(&evJ, cudaEventDisableTiming);
    }

    int nbE = (E + 255) / 256;
    int nbS = (n + 1023) / 1024;   // 49 <= 64

    // ---- fork ----
    cudaEventRecord(evF, 0);
    cudaStreamWaitEvent(sB, evF, 0);

    // main stream: CSR chain (critical path for agg1)
    count_k<<<nbE, 256>>>(ei, E);
    scan_partial_k<<<nbS, 1024>>>(n);          // produces dinv
    cudaEventRecord(evD, 0);                    // dinv ready
    scan_final_k<<<nbS, 1024>>>(n, nbS);
    fill_k<<<nbE, 256>>>(ei, E);

    // stream B: weights + gemm1 (epilogue needs dinv -> waits evD)
    convW_all_k<<<160, 256, 0, sB>>>(W1, W2, W3);
    cudaStreamWaitEvent(sB, evD, 0);
    gemm_tc<128, false><<<148, 256, SMEM128, sB>>>(x, w1h, w1l, n);
    cudaEventRecord(evJ, sB);

    // ---- join ----
    cudaStreamWaitEvent(0, evJ, 0);

    int gAgg128 = ((n * 32) + 255) / 256;
    int gAgg64  = ((n * 16) + 255) / 256;

    agg_k<128><<<gAgg128, 256>>>(b1, hH, n);

    gemm_tc<128, true><<<148, 256, SMEM128>>>(hH, w2h, w2l, n);
    agg_k<128><<<gAgg128, 256>>>(b2, hH, n);

    gemm_tc<64, true><<<148, 256, SMEM64>>>(hH, w3h, w3l, n);
    agg_k<64><<<gAgg64, 256>>>(b3, out, n);
}

// round 10
// speedup vs baseline: 1.2945x; 1.0595x over previous
#include <cuda_runtime.h>
#include <cuda_bf16.h>
#include <cuda_fp16.h>
#include <cstdint>

#define NN 50000
#define EE 800000
#define KPAD 136   // bf16 elems per SMEM row (272B) -> conflict-free fragments

// ---------------- scratch (static device globals) --------------------------
__device__ __half g_Y16[NN * 128]; // post-GEMM, dinv[row]-scaled features (fp16)
__device__ float  g_H[NN * 128];   // layer output (post-bias, fp32)
__device__ float  g_dinv[NN];
__device__ int    g_deg[NN];       // edge-only degree; zeroed by scan_final for next replay
__device__ int    g_cursor[NN];
__device__ int    g_rowptr[NN + 1];
__device__ int    g_csrc[EE];
__device__ int    g_bsum[64];
// pre-split, pre-transposed weights: [N][K=128] bf16, hi + lo parts
__device__ __nv_bfloat16 g_W1h[128 * 128], g_W1l[128 * 128];
__device__ __nv_bfloat16 g_W2h[128 * 128], g_W2l[128 * 128];
__device__ __nv_bfloat16 g_W3h[64 * 128],  g_W3l[64 * 128];

// ---------------- preprocessing (main stream) --------------------------------

__global__ void count_k(const int* __restrict__ ei, int E) {
    int e = blockIdx.x * blockDim.x + threadIdx.x;
    if (e < E) atomicAdd(&g_deg[ei[E + e]], 1);
}

__global__ void scan_partial_k(int n) {
    __shared__ int sm[32];
    int tid = threadIdx.x;
    int i = blockIdx.x * 1024 + tid;
    int v = 0;
    if (i < n) {
        v = g_deg[i];
        g_dinv[i] = rsqrtf((float)(v + 1));
    }
    int vv = v;
    #pragma unroll
    for (int o = 16; o > 0; o >>= 1) vv += __shfl_down_sync(0xffffffffu, vv, o);
    int lane = tid & 31, wid = tid >> 5;
    if (lane == 0) sm[wid] = vv;
    __syncthreads();
    if (wid == 0) {
        vv = sm[lane];
        #pragma unroll
        for (int o = 16; o > 0; o >>= 1) vv += __shfl_down_sync(0xffffffffu, vv, o);
        if (lane == 0) g_bsum[blockIdx.x] = vv;
    }
}

__global__ void scan_final_k(int n, int nbS) {
    __shared__ int sm[1024];
    __shared__ int s_off;
    int tid = threadIdx.x;
    int bid = blockIdx.x;
    int i = bid * 1024 + tid;

    if (tid < 32) {
        int a = (tid      < bid) ? g_bsum[tid]      : 0;
        int b = (tid + 32 < bid) ? g_bsum[tid + 32] : 0;
        int s = a + b;
        #pragma unroll
        for (int o = 16; o > 0; o >>= 1) s += __shfl_down_sync(0xffffffffu, s, o);
        if (tid == 0) s_off = s;
    }

    int v = 0;
    if (i < n) {
        v = g_deg[i];
        g_deg[i] = 0;
    }
    sm[tid] = v;
    __syncthreads();
    #pragma unroll
    for (int off = 1; off < 1024; off <<= 1) {
        int t = 0;
        if (tid >= off) t = sm[tid - off];
        __syncthreads();
        if (tid >= off) sm[tid] += t;
        __syncthreads();
    }
    int incl = sm[tid];
    if (i < n) {
        int rp = s_off + incl - v;
        g_rowptr[i] = rp;
        g_cursor[i] = rp;
        if (i == n - 1) g_rowptr[n] = s_off + incl;
    }
}

__global__ void fill_k(const int* __restrict__ ei, int E) {
    int e = blockIdx.x * blockDim.x + threadIdx.x;
    if (e < E) {
        int s = ei[e];
        int d = ei[E + e];
        int pos = atomicAdd(&g_cursor[d], 1);
        g_csrc[pos] = s;
    }
}

// ---------------- weight conversion (stream B) -------------------------------
__device__ __forceinline__ void conv_one(const float* W, __nv_bfloat16* Wh,
                                         __nv_bfloat16* Wl, int F, int idx) {
    int nn = idx >> 7, k = idx & 127;
    float v = W[k * F + nn];
    __nv_bfloat16 h = __float2bfloat16(v);
    __nv_bfloat16 l = __float2bfloat16(v - __bfloat162float(h));
    Wh[nn * 128 + k] = h;
    Wl[nn * 128 + k] = l;
}

__global__ void convW_all_k(const float* __restrict__ W1,
                            const float* __restrict__ W2,
                            const float* __restrict__ W3) {
    int idx = blockIdx.x * blockDim.x + threadIdx.x;
    if (idx < 16384)       conv_one(W1, g_W1h, g_W1l, 128, idx);
    else if (idx < 32768)  conv_one(W2, g_W2h, g_W2l, 128, idx - 16384);
    else if (idx < 40960)  conv_one(W3, g_W3h, g_W3l, 64,  idx - 32768);
}

// ---------------- tensor-core GEMM ------------------------------------------
// Y16[n,F] = half((relu?(A[n,128]) @ W[128,F]) * dinv[row]),  bf16x3 split.

__device__ __forceinline__ unsigned packbf(float a, float b) {
    __nv_bfloat162 p = __floats2bfloat162_rn(a, b);
    return *reinterpret_cast<unsigned*>(&p);
}

__device__ __forceinline__ void mma_bf16(float* c,
                                         unsigned a0, unsigned a1, unsigned a2, unsigned a3,
                                         unsigned b0, unsigned b1) {
    asm volatile(
        "mma.sync.aligned.m16n8k16.row.col.f32.bf16.bf16.f32 "
        "{%0,%1,%2,%3}, {%4,%5,%6,%7}, {%8,%9}, {%0,%1,%2,%3};"
        : "+f"(c[0]), "+f"(c[1]), "+f"(c[2]), "+f"(c[3])
        : "r"(a0), "r"(a1), "r"(a2), "r"(a3), "r"(b0), "r"(b1));
}

template <int F, bool RELU>
__global__ __launch_bounds__(256)
void gemm_tc(const float* __restrict__ A,
             const __nv_bfloat16* __restrict__ Wh,
             const __nv_bfloat16* __restrict__ Wl, int n) {
    extern __shared__ unsigned char smraw[];
    __nv_bfloat16* sWh = (__nv_bfloat16*)smraw;        // F * KPAD
    __nv_bfloat16* sWl = sWh + F * KPAD;
    __nv_bfloat16* sAh = sWl + F * KPAD;               // 128 * KPAD
    __nv_bfloat16* sAl = sAh + 128 * KPAD;

    const int NT = F / 16;
    int tid = threadIdx.x;
    int wid = tid >> 5, lane = tid & 31;
    int g = lane >> 2, t = lane & 3;
    int wm = wid >> 1;
    int wn = wid & 1;
    int arow = wm * 32;
    int bcol0 = wn * (F / 2);

    {
        const unsigned* gwh = (const unsigned*)Wh;
        const unsigned* gwl = (const unsigned*)Wl;
        for (int i = tid; i < F * 64; i += 256) {
            int r = i >> 6, c = i & 63;
            ((unsigned*)(sWh + r * KPAD))[c] = gwh[i];
            ((unsigned*)(sWl + r * KPAD))[c] = gwl[i];
        }
    }

    int ntiles = (n + 127) >> 7;
    for (int tile = blockIdx.x; tile < ntiles; tile += gridDim.x) {
        __syncthreads();
        int r0 = tile * 128;

        for (int i = tid; i < 4096; i += 256) {
            int r = i >> 5, c4 = i & 31;
            int row = r0 + r;
            float4 v = make_float4(0.f, 0.f, 0.f, 0.f);
            if (row < n) v = *(const float4*)(A + (size_t)row * 128 + c4 * 4);
            if (RELU) {
                v.x = fmaxf(v.x, 0.f); v.y = fmaxf(v.y, 0.f);
                v.z = fmaxf(v.z, 0.f); v.w = fmaxf(v.w, 0.f);
            }
            __nv_bfloat16 h0 = __float2bfloat16(v.x), h1 = __float2bfloat16(v.y);
            __nv_bfloat16 h2 = __float2bfloat16(v.z), h3 = __float2bfloat16(v.w);
            float l0 = v.x - __bfloat162float(h0), l1 = v.y - __bfloat162float(h1);
            float l2 = v.z - __bfloat162float(h2), l3 = v.w - __bfloat162float(h3);
            unsigned h01, h23;
            { __nv_bfloat162 p0 = {h0, h1}; h01 = *reinterpret_cast<unsigned*>(&p0);
              __nv_bfloat162 p1 = {h2, h3}; h23 = *reinterpret_cast<unsigned*>(&p1); }
            unsigned l01 = packbf(l0, l1), l23 = packbf(l2, l3);
            *reinterpret_cast<uint2*>(sAh + r * KPAD + c4 * 4) = make_uint2(h01, h23);
            *reinterpret_cast<uint2*>(sAl + r * KPAD + c4 * 4) = make_uint2(l01, l23);
        }
        __syncthreads();

        float acc[2][NT][4];
        #pragma unroll
        for (int rb = 0; rb < 2; rb++)
            #pragma unroll
            for (int j = 0; j < NT; j++) {
                acc[rb][j][0] = 0.f; acc[rb][j][1] = 0.f;
                acc[rb][j][2] = 0.f; acc[rb][j][3] = 0.f;
            }

        #pragma unroll
        for (int kk = 0; kk < 128; kk += 16) {
            unsigned ah[2][4], al[2][4];
            #pragma unroll
            for (int rb = 0; rb < 2; rb++) {
                int br = arow + rb * 16;
                ah[rb][0] = *(const unsigned*)(sAh + (br + g)     * KPAD + kk + 2 * t);
                ah[rb][1] = *(const unsigned*)(sAh + (br + g + 8) * KPAD + kk + 2 * t);
                ah[rb][2] = *(const unsigned*)(sAh + (br + g)     * KPAD + kk + 8 + 2 * t);
                ah[rb][3] = *(const unsigned*)(sAh + (br + g + 8) * KPAD + kk + 8 + 2 * t);
                al[rb][0] = *(const unsigned*)(sAl + (br + g)     * KPAD + kk + 2 * t);
                al[rb][1] = *(const unsigned*)(sAl + (br + g + 8) * KPAD + kk + 2 * t);
                al[rb][2] = *(const unsigned*)(sAl + (br + g)     * KPAD + kk + 8 + 2 * t);
                al[rb][3] = *(const unsigned*)(sAl + (br + g + 8) * KPAD + kk + 8 + 2 * t);
            }
            #pragma unroll
            for (int j = 0; j < NT; j++) {
                int bn = bcol0 + j * 8 + g;
                unsigned b0h = *(const unsigned*)(sWh + bn * KPAD + kk + 2 * t);
                unsigned b1h = *(const unsigned*)(sWh + bn * KPAD + kk + 8 + 2 * t);
                unsigned b0l = *(const unsigned*)(sWl + bn * KPAD + kk + 2 * t);
                unsigned b1l = *(const unsigned*)(sWl + bn * KPAD + kk + 8 + 2 * t);
                #pragma unroll
                for (int rb = 0; rb < 2; rb++) {
                    mma_bf16(acc[rb][j], ah[rb][0], ah[rb][1], ah[rb][2], ah[rb][3], b0h, b1h);
                    mma_bf16(acc[rb][j], ah[rb][0], ah[rb][1], ah[rb][2], ah[rb][3], b0l, b1l);
                    mma_bf16(acc[rb][j], al[rb][0], al[rb][1], al[rb][2], al[rb][3], b0h, b1h);
                }
            }
        }

        // epilogue: scale by dinv[row], write Y as fp16
        #pragma unroll
        for (int rb = 0; rb < 2; rb++) {
            int row0 = r0 + arow + rb * 16 + g;
            int row1 = row0 + 8;
            float d0 = (row0 < n) ? g_dinv[row0] : 0.f;
            float d1 = (row1 < n) ? g_dinv[row1] : 0.f;
            #pragma unroll
            for (int j = 0; j < NT; j++) {
                int col = bcol0 + j * 8 + 2 * t;
                if (row0 < n) {
                    __half2 p = __floats2half2_rn(acc[rb][j][0] * d0, acc[rb][j][1] * d0);
                    *(__half2*)(g_Y16 + (size_t)row0 * F + col) = p;
                }
                if (row1 < n) {
                    __half2 p = __floats2half2_rn(acc[rb][j][2] * d1, acc[rb][j][3] * d1);
                    *(__half2*)(g_Y16 + (size_t)row1 * F + col) = p;
                }
            }
        }
    }
}

// ---------------- aggregation ------------------------------------------------
// out[i] = dinv[i]*(Y[i] + sum Y[src]) + b  ; Y gathered in fp16, summed fp32.
__device__ __forceinline__ void acc8(float* a, uint4 r) {
    float2 f0 = __half22float2(*reinterpret_cast<__half2*>(&r.x));
    float2 f1 = __half22float2(*reinterpret_cast<__half2*>(&r.y));
    float2 f2 = __half22float2(*reinterpret_cast<__half2*>(&r.z));
    float2 f3 = __half22float2(*reinterpret_cast<__half2*>(&r.w));
    a[0] += f0.x; a[1] += f0.y; a[2] += f1.x; a[3] += f1.y;
    a[4] += f2.x; a[5] += f2.y; a[6] += f3.x; a[7] += f3.y;
}

template <int F>
__global__ __launch_bounds__(256)
void agg_k(const float* __restrict__ bias, float* __restrict__ out, int n) {
    const int L = F / 8;                               // lanes per node (16 / 8)
    int lane = threadIdx.x & (L - 1);
    int node = (blockIdx.x * blockDim.x + threadIdx.x) / L;
    if (node >= n) return;

    unsigned mask = ((L == 32) ? 0xffffffffu
                               : (((1u << L) - 1u) << (((threadIdx.x & 31) / L) * L)));

    int s = g_rowptr[node];
    int e = g_rowptr[node + 1];

    float a[4][8];
    {
        uint4 r = *(const uint4*)(g_Y16 + (size_t)node * F + lane * 8);  // self loop
        #pragma unroll
        for (int q = 0; q < 8; q++) a[0][q] = 0.f;
        acc8(a[0], r);
        #pragma unroll
        for (int q = 0; q < 8; q++) { a[1][q] = 0.f; a[2][q] = 0.f; a[3][q] = 0.f; }
    }

    for (int base = s; base < e; base += L) {
        int idx = base + lane;
        int v = (idx < e) ? g_csrc[idx] : 0;
        int cnt = min(L, e - base);
        int tt = 0;
        for (; tt + 4 <= cnt; tt += 4) {
            int s0 = __shfl_sync(mask, v, tt,     L);
            int s1 = __shfl_sync(mask, v, tt + 1, L);
            int s2 = __shfl_sync(mask, v, tt + 2, L);
            int s3 = __shfl_sync(mask, v, tt + 3, L);
            uint4 r0 = *(const uint4*)(g_Y16 + (size_t)s0 * F + lane * 8);
            uint4 r1 = *(const uint4*)(g_Y16 + (size_t)s1 * F + lane * 8);
            uint4 r2 = *(const uint4*)(g_Y16 + (size_t)s2 * F + lane * 8);
            uint4 r3 = *(const uint4*)(g_Y16 + (size_t)s3 * F + lane * 8);
            acc8(a[0], r0); acc8(a[1], r1); acc8(a[2], r2); acc8(a[3], r3);
        }
        for (; tt < cnt; tt++) {
            int sc = __shfl_sync(mask, v, tt, L);
            uint4 r = *(const uint4*)(g_Y16 + (size_t)sc * F + lane * 8);
            acc8(a[0], r);
        }
    }

    float d = g_dinv[node];
    float4 b0 = *(const float4*)(bias + lane * 8);
    float4 b1 = *(const float4*)(bias + lane * 8 + 4);
    float o[8];
    #pragma unroll
    for (int q = 0; q < 8; q++) {
        float sum = (a[0][q] + a[1][q]) + (a[2][q] + a[3][q]);
        o[q] = sum * d;
    }
    o[0] += b0.x; o[1] += b0.y; o[2] += b0.z; o[3] += b0.w;
    o[4] += b1.x; o[5] += b1.y; o[6] += b1.z; o[7] += b1.w;
    *(float4*)(out + (size_t)node * F + lane * 8)     = make_float4(o[0], o[1], o[2], o[3]);
    *(float4*)(out + (size_t)node * F + lane * 8 + 4) = make_float4(o[4], o[5], o[6], o[7]);
}

// ---------------- launch -----------------------------------------------------

extern "C" void kernel_launch(void* const* d_in, const int* in_sizes, int n_in,
                              void* d_out, int out_size) {
    const float* x  = (const float*)d_in[0];
    const int*   ei = (const int*)d_in[1];   // int32
    const float* W1 = (const float*)d_in[2];
    const float* b1 = (const float*)d_in[3];
    const float* W2 = (const float*)d_in[4];
    const float* b2 = (const float*)d_in[5];
    const float* W3 = (const float*)d_in[6];
    const float* b3 = (const float*)d_in[7];
    float* out = (float*)d_out;

    float* hH = nullptr;
    cudaGetSymbolAddress((void**)&hH, g_H);
    __nv_bfloat16 *w1h, *w1l, *w2h, *w2l, *w3h, *w3l;
    cudaGetSymbolAddress((void**)&w1h, g_W1h);
    cudaGetSymbolAddress((void**)&w1l, g_W1l);
    cudaGetSymbolAddress((void**)&w2h, g_W2h);
    cudaGetSymbolAddress((void**)&w2l, g_W2l);
    cudaGetSymbolAddress((void**)&w3h, g_W3h);
    cudaGetSymbolAddress((void**)&w3l, g_W3l);

    int n = in_sizes[0] / 128;
    int E = in_sizes[1] / 2;

    const int SMEM128 = 4 * KPAD * (128 + 128);  // 139264 B
    const int SMEM64  = 4 * KPAD * (64  + 128);  // 104448 B
    cudaFuncSetAttribute(gemm_tc<128, false>, cudaFuncAttributeMaxDynamicSharedMemorySize, SMEM128);
    cudaFuncSetAttribute(gemm_tc<128, true>,  cudaFuncAttributeMaxDynamicSharedMemorySize, SMEM128);
    cudaFuncSetAttribute(gemm_tc<64,  true>,  cudaFuncAttributeMaxDynamicSharedMemorySize, SMEM64);

    // side stream + events (created once on the un-captured correctness call)
    static cudaStream_t sB = nullptr;
    static cudaEvent_t  evF = nullptr, evD = nullptr, evJ = nullptr;
    if (sB == nullptr) {
        cudaStreamCreateWithFlags(&sB, cudaStreamNonBlocking);
        cudaEventCreateWithFlags(&evF, cudaEventDisableTiming);
        cudaEventCreateWithFlags(&evD, cudaEventDisableTiming);
        cudaEventCreateWithFlags(&evJ, cudaEventDisableTiming);
    }

    int nbE = (E + 255) / 256;
    int nbS = (n + 1023) / 1024;   // 49 <= 64

    // ---- fork ----
    cudaEventRecord(evF, 0);
    cudaStreamWaitEvent(sB, evF, 0);

    // main stream: CSR chain (critical path for agg1)
    count_k<<<nbE, 256>>>(ei, E);
    scan_partial_k<<<nbS, 1024>>>(n);          // produces dinv
    cudaEventRecord(evD, 0);                    // dinv ready
    scan_final_k<<<nbS, 1024>>>(n, nbS);
    fill_k<<<nbE, 256>>>(ei, E);

    // stream B: weights + gemm1 (epilogue needs dinv -> waits evD)
    convW_all_k<<<160, 256, 0, sB>>>(W1, W2, W3);
    cudaStreamWaitEvent(sB, evD, 0);
    gemm_tc<128, false><<<148, 256, SMEM128, sB>>>(x, w1h, w1l, n);
    cudaEventRecord(evJ, sB);

    // ---- join ----
    cudaStreamWaitEvent(0, evJ, 0);

    int gAgg128 = ((n * 16) + 255) / 256;   // L=16 lanes per node
    int gAgg64  = ((n * 8)  + 255) / 256;   // L=8

    agg_k<128><<<gAgg128, 256>>>(b1, hH, n);

    gemm_tc<128, true><<<148, 256, SMEM128>>>(hH, w2h, w2l, n);
    agg_k<128><<<gAgg128, 256>>>(b2, hH, n);

    gemm_tc<64, true><<<148, 256, SMEM64>>>(hH, w3h, w3l, n);
    agg_k<64><<<gAgg64, 256>>>(b3, out, n);
}